// round 7
// baseline (speedup 1.0000x reference)
#include <cuda_runtime.h>
#include <cuda_fp16.h>
#include <cuda_bf16.h>

#define NN 50000
#define NE 800000
#define IND 128
#define HID 64

// ---------------- scratch (device globals; no runtime allocation) ----------
__device__ int    g_deg_in[NN];
__device__ int    g_deg_out[NN];
__device__ int    g_row_beg[NN];
__device__ int    g_cursor[NN];
__device__ int    g_total;
__device__ int    g_esrc[NE];
__device__ float  g_din[NN];
__device__ float  g_dout[NN];
__device__ float  g_bufB[NN * IND];   // gcn t1 (128-dim)
__device__ float  g_h [NN * HID];
__device__ float  g_f1[NN * HID];
__device__ float  g_f2[NN * HID];
__device__ float  g_s [NN * HID];
__device__ float  g_Wa[HID * HID];
__device__ float  g_Wb[HID * HID];
__device__ float  g_Wc[HID * HID];
// fp16 gather tables
__device__ __half g_in16[NN * IND];
__device__ __half g_h16 [NN * HID];
__device__ __half g_f116[NN * HID];
__device__ __half g_s16 [NN * HID];

// ---------------- packed fp32x2 FMA (Blackwell FFMA2) ----------------------
__device__ __forceinline__ float2 f2fma(float2 a, float2 b, float2 c) {
    unsigned long long ua = *reinterpret_cast<unsigned long long*>(&a);
    unsigned long long ub = *reinterpret_cast<unsigned long long*>(&b);
    unsigned long long uc = *reinterpret_cast<unsigned long long*>(&c);
    unsigned long long ud;
    asm("fma.rn.f32x2 %0, %1, %2, %3;" : "=l"(ud) : "l"(ua), "l"(ub), "l"(uc));
    return *reinterpret_cast<float2*>(&ud);
}

// ---------------- graph prep ----------------
__global__ void k_zero_deg() {
    int i = blockIdx.x * blockDim.x + threadIdx.x;
    if (i < NN) { g_deg_in[i] = 0; g_deg_out[i] = 0; }
    if (i == 0) g_total = 0;
}

__global__ void k_deg(const int* __restrict__ src, const int* __restrict__ dst) {
    int e = blockIdx.x * blockDim.x + threadIdx.x;
    if (e < NE) {
        atomicAdd(&g_deg_in[dst[e]], 1);
        atomicAdd(&g_deg_out[src[e]], 1);
    }
}

// segment offsets via atomic allocation (segment order irrelevant) + deg norms
__global__ void k_offsets() {
    int i = blockIdx.x * blockDim.x + threadIdx.x;
    if (i < NN) {
        int d = g_deg_in[i];
        int pos = atomicAdd(&g_total, d);
        g_row_beg[i] = pos;
        g_cursor[i]  = pos;
        g_din[i]  = rsqrtf((float)max(d, 1));
        g_dout[i] = rsqrtf((float)max(g_deg_out[i], 1));
    }
}

__global__ void k_scatter(const int* __restrict__ src, const int* __restrict__ dst) {
    int e = blockIdx.x * blockDim.x + threadIdx.x;
    if (e < NE) {
        int v = dst[e];
        int pos = atomicAdd(&g_cursor[v], 1);
        g_esrc[pos] = src[e];
    }
}

// Wa = 3*W3_0 ; Wb = -3*W3_0 + 3*W3_1 + W3_3 ; Wc = .75*W3_0 -1.5*W3_1 + .75*W3_2 + W3_4
__global__ void k_wabc(const float* __restrict__ W3) {
    int i = blockIdx.x * blockDim.x + threadIdx.x;
    if (i < HID * HID) {
        int k = i >> 6, c = i & 63;
        float w0 = W3[(k      ) * 64 + c];
        float w1 = W3[(64  + k) * 64 + c];
        float w2 = W3[(128 + k) * 64 + c];
        float w3 = W3[(192 + k) * 64 + c];
        float w4 = W3[(256 + k) * 64 + c];
        g_Wa[i] = 3.0f * w0;
        g_Wb[i] = -3.0f * w0 + 3.0f * w1 + w3;
        g_Wc[i] = 0.75f * w0 - 1.5f * w1 + 0.75f * w2 + w4;
    }
}

// ---------------- fp32 -> fp16 convert (for in_feat) -----------------------
__global__ void k_cvt(const float4* __restrict__ x, uint2* __restrict__ y, int n4) {
    int i = blockIdx.x * blockDim.x + threadIdx.x;
    if (i < n4) {
        float4 t = x[i];
        __half2 lo = __floats2half2_rn(t.x, t.y);
        __half2 hi = __floats2half2_rn(t.z, t.w);
        uint2 o;
        o.x = *reinterpret_cast<unsigned*>(&lo);
        o.y = *reinterpret_cast<unsigned*>(&hi);
        y[i] = o;
    }
}

// ---------------- spmm, fp16 gather, fp32 accumulate (warp per node) -------
// acc = sum_{u in N(v)} x16[u,:] * gsc[u]
// mode 1: y[v] = base[v] - din[v]*acc   (Laplacian); optionally emit y16
// mode 0: y[v] = din[v]*acc             (GCN norm)
__global__ void k_spmm64h(const __half2* __restrict__ x16, const float* __restrict__ gsc,
                          const float* __restrict__ base, float* __restrict__ y,
                          __half2* __restrict__ y16, int mode) {
    int w = (blockIdx.x * blockDim.x + threadIdx.x) >> 5;
    int lane = threadIdx.x & 31;
    if (w >= NN) return;
    int beg = g_row_beg[w];
    int end = beg + g_deg_in[w];
    float2 acc = make_float2(0.f, 0.f);
    #pragma unroll 4
    for (int j = beg; j < end; j++) {
        int u = g_esrc[j];
        float s = gsc[u];
        float2 t = __half22float2(x16[u * 32 + lane]);
        acc.x += t.x * s;
        acc.y += t.y * s;
    }
    float sd = g_din[w];
    float2 r;
    if (mode) {
        float2 b = *reinterpret_cast<const float2*>(base + w * 64 + lane * 2);
        r.x = b.x - acc.x * sd;
        r.y = b.y - acc.y * sd;
    } else {
        r.x = acc.x * sd;
        r.y = acc.y * sd;
    }
    *reinterpret_cast<float2*>(y + w * 64 + lane * 2) = r;
    if (y16) y16[w * 32 + lane] = __floats2half2_rn(r.x, r.y);
}

__global__ void k_spmm128h(const uint2* __restrict__ x16, const float* __restrict__ gsc,
                           float* __restrict__ y) {
    int w = (blockIdx.x * blockDim.x + threadIdx.x) >> 5;
    int lane = threadIdx.x & 31;
    if (w >= NN) return;
    int beg = g_row_beg[w];
    int end = beg + g_deg_in[w];
    float4 acc = make_float4(0.f, 0.f, 0.f, 0.f);
    #pragma unroll 4
    for (int j = beg; j < end; j++) {
        int u = g_esrc[j];
        float s = gsc[u];
        uint2 p = x16[u * 32 + lane];
        float2 lo = __half22float2(*reinterpret_cast<__half2*>(&p.x));
        float2 hi = __half22float2(*reinterpret_cast<__half2*>(&p.y));
        acc.x += lo.x * s; acc.y += lo.y * s;
        acc.z += hi.x * s; acc.w += hi.y * s;
    }
    float sd = g_din[w];
    acc.x *= sd; acc.y *= sd; acc.z *= sd; acc.w *= sd;
    *reinterpret_cast<float4*>(y + w * 128 + lane * 4) = acc;
}

// ---------------- fp32x2 tiled GEMM: C = epi(A[M,K] @ B[K,N]) --------------
#define GF_BIAS 2
#define GF_RELU 4
#define KT 32

#define GEMM_INNER(As2, Bs, acc, tx, ty)                                     \
    _Pragma("unroll")                                                        \
    for (int kk = 0; kk < KT; kk += 4) {                                     \
        float4 a4[4];                                                        \
        _Pragma("unroll")                                                    \
        for (int i = 0; i < 4; i++)                                          \
            a4[i] = *reinterpret_cast<const float4*>(&As2[ty * 4 + i][kk]);  \
        _Pragma("unroll")                                                    \
        for (int q = 0; q < 4; q++) {                                        \
            float4 bv = *reinterpret_cast<const float4*>(&Bs[kk + q][tx * 4]); \
            float2 b01 = make_float2(bv.x, bv.y);                            \
            float2 b23 = make_float2(bv.z, bv.w);                            \
            _Pragma("unroll")                                                \
            for (int i = 0; i < 4; i++) {                                    \
                float a = (q == 0) ? a4[i].x : (q == 1) ? a4[i].y             \
                        : (q == 2) ? a4[i].z : a4[i].w;                      \
                float2 aa = make_float2(a, a);                               \
                acc[i][0] = f2fma(aa, b01, acc[i][0]);                       \
                acc[i][1] = f2fma(aa, b23, acc[i][1]);                       \
            }                                                                \
        }                                                                    \
    }

__global__ void __launch_bounds__(256)
k_gemm(const float* __restrict__ A, const float* __restrict__ B,
       const float* __restrict__ bias, float* __restrict__ C,
       __half* __restrict__ Ch, int M, int K, int N, int flags) {
    __shared__ float As2[64][KT + 4];
    __shared__ float Bs[KT][68];
    int tid = threadIdx.x;
    int tx = tid & 15;
    int ty = tid >> 4;
    int rowBase = blockIdx.y * 64;
    int colBase = blockIdx.x * 64;
    float2 acc[4][2] = {};
    for (int k0 = 0; k0 < K; k0 += KT) {
        #pragma unroll 2
        for (int l = tid; l < 512; l += 256) {
            int r = l >> 3, ks = (l & 7) << 2;
            int row = rowBase + r;
            float4 v = make_float4(0.f, 0.f, 0.f, 0.f);
            if (row < M) v = *reinterpret_cast<const float4*>(A + (size_t)row * K + k0 + ks);
            *reinterpret_cast<float4*>(&As2[r][ks]) = v;
        }
        #pragma unroll 2
        for (int l = tid; l < 512; l += 256) {
            int kk = l >> 4, c = (l & 15) << 2;
            *reinterpret_cast<float4*>(&Bs[kk][c]) =
                *reinterpret_cast<const float4*>(B + (size_t)(k0 + kk) * N + colBase + c);
        }
        __syncthreads();
        GEMM_INNER(As2, Bs, acc, tx, ty)
        __syncthreads();
    }
    int col0 = colBase + tx * 4;
    float4 bb = make_float4(0.f, 0.f, 0.f, 0.f);
    if (flags & GF_BIAS) bb = *reinterpret_cast<const float4*>(bias + col0);
    #pragma unroll
    for (int i = 0; i < 4; i++) {
        int row = rowBase + ty * 4 + i;
        if (row >= M) continue;
        float4 v = make_float4(acc[i][0].x + bb.x, acc[i][0].y + bb.y,
                               acc[i][1].x + bb.z, acc[i][1].y + bb.w);
        if (flags & GF_RELU) {
            v.x = fmaxf(v.x, 0.f); v.y = fmaxf(v.y, 0.f);
            v.z = fmaxf(v.z, 0.f); v.w = fmaxf(v.w, 0.f);
        }
        *reinterpret_cast<float4*>(C + (size_t)row * N + col0) = v;
        if (Ch) {
            __half2 lo = __floats2half2_rn(v.x, v.y);
            __half2 hi = __floats2half2_rn(v.z, v.w);
            uint2 o;
            o.x = *reinterpret_cast<unsigned*>(&lo);
            o.y = *reinterpret_cast<unsigned*>(&hi);
            *reinterpret_cast<uint2*>(Ch + (size_t)row * N + col0) = o;
        }
    }
}

// ---------------- fused head: out = relu(h@Wa + f1@Wb + f2@Wc + b3) @ W4 + b4
__global__ void __launch_bounds__(256)
k_head_fused(const float* __restrict__ b3, const float* __restrict__ W4,
             const float* __restrict__ b4, float* __restrict__ out) {
    __shared__ float As2[64][KT + 4];
    __shared__ float Bs[KT][68];
    int tid = threadIdx.x;
    int tx = tid & 15;
    int ty = tid >> 4;
    int rowBase = blockIdx.x * 64;
    float2 acc[4][2] = {};
    const float* Asrc[3] = { g_h, g_f1, g_f2 };
    const float* Bsrc[3] = { g_Wa, g_Wb, g_Wc };
    for (int s3 = 0; s3 < 3; s3++) {
        const float* A = Asrc[s3];
        const float* B = Bsrc[s3];
        for (int k0 = 0; k0 < 64; k0 += KT) {
            #pragma unroll 2
            for (int l = tid; l < 512; l += 256) {
                int r = l >> 3, ks = (l & 7) << 2;
                int row = rowBase + r;
                float4 v = make_float4(0.f, 0.f, 0.f, 0.f);
                if (row < NN) v = *reinterpret_cast<const float4*>(A + (size_t)row * 64 + k0 + ks);
                *reinterpret_cast<float4*>(&As2[r][ks]) = v;
            }
            #pragma unroll 2
            for (int l = tid; l < 512; l += 256) {
                int kk = l >> 4, c = (l & 15) << 2;
                *reinterpret_cast<float4*>(&Bs[kk][c]) =
                    *reinterpret_cast<const float4*>(B + (size_t)(k0 + kk) * 64 + c);
            }
            __syncthreads();
            GEMM_INNER(As2, Bs, acc, tx, ty)
            __syncthreads();
        }
    }
    int col0 = tx * 4;
    float4 bb = *reinterpret_cast<const float4*>(b3 + col0);
    float w40[4], w41[4];
    #pragma unroll
    for (int jj = 0; jj < 4; jj++) {
        w40[jj] = W4[(col0 + jj) * 2];
        w41[jj] = W4[(col0 + jj) * 2 + 1];
    }
    float o0 = b4[0], o1 = b4[1];
    #pragma unroll
    for (int i = 0; i < 4; i++) {
        float z0 = fmaxf(acc[i][0].x + bb.x, 0.f);
        float z1 = fmaxf(acc[i][0].y + bb.y, 0.f);
        float z2 = fmaxf(acc[i][1].x + bb.z, 0.f);
        float z3 = fmaxf(acc[i][1].y + bb.w, 0.f);
        float p0 = z0 * w40[0] + z1 * w40[1] + z2 * w40[2] + z3 * w40[3];
        float p1 = z0 * w41[0] + z1 * w41[1] + z2 * w41[2] + z3 * w41[3];
        #pragma unroll
        for (int off = 8; off >= 1; off >>= 1) {
            p0 += __shfl_down_sync(0xffffffffu, p0, off, 16);
            p1 += __shfl_down_sync(0xffffffffu, p1, off, 16);
        }
        int row = rowBase + ty * 4 + i;
        if (tx == 0 && row < NN) {
            out[row * 2]     = p0 + o0;
            out[row * 2 + 1] = p1 + o1;
        }
    }
}

// ---------------- launch ----------------
extern "C" void kernel_launch(void* const* d_in, const int* in_sizes, int n_in,
                              void* d_out, int out_size) {
    const float* in_feat = (const float*)d_in[0];
    const int*   src     = (const int*)d_in[1];
    const int*   dst     = (const int*)d_in[2];
    const float* W1 = (const float*)d_in[3];
    const float* b1 = (const float*)d_in[4];
    const float* W2 = (const float*)d_in[5];
    const float* b2 = (const float*)d_in[6];
    const float* W3 = (const float*)d_in[7];
    const float* b3 = (const float*)d_in[8];
    const float* W4 = (const float*)d_in[9];
    const float* b4 = (const float*)d_in[10];
    const float* Wg1 = (const float*)d_in[11];
    const float* bg1 = (const float*)d_in[12];
    const float* Wg2 = (const float*)d_in[13];
    const float* bg2 = (const float*)d_in[14];

    float* out = (float*)d_out;          // [NN,2]
    float* emb = out + NN * 2;           // [NN,128]

    float  *p_h, *p_f1, *p_f2, *p_s, *p_bufB, *p_din, *p_dout;
    __half *p_in16, *p_h16, *p_f116, *p_s16;
    cudaGetSymbolAddress((void**)&p_h,    g_h);
    cudaGetSymbolAddress((void**)&p_f1,   g_f1);
    cudaGetSymbolAddress((void**)&p_f2,   g_f2);
    cudaGetSymbolAddress((void**)&p_s,    g_s);
    cudaGetSymbolAddress((void**)&p_bufB, g_bufB);
    cudaGetSymbolAddress((void**)&p_din,  g_din);
    cudaGetSymbolAddress((void**)&p_dout, g_dout);
    cudaGetSymbolAddress((void**)&p_in16, g_in16);
    cudaGetSymbolAddress((void**)&p_h16,  g_h16);
    cudaGetSymbolAddress((void**)&p_f116, g_f116);
    cudaGetSymbolAddress((void**)&p_s16,  g_s16);

    const int TB = 256;
    int nBlkN = (NN + TB - 1) / TB;
    int nBlkE = (NE + TB - 1) / TB;
    int spmmBlocks = (NN * 32 + TB - 1) / TB;

    // ---- graph prep ----
    k_zero_deg<<<nBlkN, TB>>>();
    k_deg<<<nBlkE, TB>>>(src, dst);
    k_offsets<<<nBlkN, TB>>>();
    k_scatter<<<nBlkE, TB>>>(src, dst);
    k_wabc<<<16, TB>>>(W3);
    k_cvt<<<(NN * 32 + TB - 1) / TB, TB>>>((const float4*)in_feat, (uint2*)p_in16, NN * 32);

    dim3 g64(1, (NN + 63) / 64);
    dim3 g128(2, (NN + 63) / 64);
    int hBlocks = (NN + 63) / 64;

    // ---- MLP front end: h = relu(relu(X@W1+b1)@W2+b2)  (h also in fp16) ----
    k_gemm<<<g64, 256>>>(in_feat, W1, b1, p_s, nullptr, NN, 128, 64, GF_BIAS | GF_RELU);
    k_gemm<<<g64, 256>>>(p_s, W2, b2, p_h, p_h16, NN, 64, 64, GF_BIAS | GF_RELU);

    // ---- f1 = L h ; f2 = L f1 (fp16 gathers, fp32 accum) ----
    k_spmm64h<<<spmmBlocks, TB>>>((const __half2*)p_h16,  p_din, p_h,  p_f1, (__half2*)p_f116, 1);
    k_spmm64h<<<spmmBlocks, TB>>>((const __half2*)p_f116, p_din, p_f1, p_f2, nullptr, 1);

    // ---- fused head: out = relu(h@Wa + f1@Wb + f2@Wc + b3) @ W4 + b4 ----
    k_head_fused<<<hBlocks, 256>>>(b3, W4, b4, out);

    // ---- GCN branch ----
    k_spmm128h<<<spmmBlocks, TB>>>((const uint2*)p_in16, p_dout, p_bufB);
    k_gemm<<<g64, 256>>>(p_bufB, Wg1, bg1, p_s, p_s16, NN, 128, 64, GF_BIAS | GF_RELU);
    k_spmm64h<<<spmmBlocks, TB>>>((const __half2*)p_s16, p_dout, nullptr, p_f1, nullptr, 0);
    k_gemm<<<g128, 256>>>(p_f1, Wg2, bg2, emb, nullptr, NN, 64, 128, GF_BIAS);
}

// round 8
// speedup vs baseline: 1.1820x; 1.1820x over previous
#include <cuda_runtime.h>
#include <cuda_fp16.h>
#include <cuda_bf16.h>

#define NN 50000
#define NE 800000
#define IND 128
#define HID 64

// ---------------- scratch (device globals; no runtime allocation) ----------
__device__ int    g_deg_in[NN];
__device__ int    g_deg_out[NN];
__device__ int    g_row_beg[NN];
__device__ int    g_cursor[NN];
__device__ int    g_total;
__device__ int    g_esrc[NE];
__device__ float  g_din[NN];
__device__ float  g_dout[NN];
__device__ float  g_bufB[NN * IND];   // gcn: spmm128 out (128-dim)
__device__ float  g_bufA[NN * HID];   // gcn: relu(gconv1) fp32
__device__ float  g_bufC[NN * HID];   // gcn: spmm64 out
__device__ float  g_h [NN * HID];
__device__ float  g_f1[NN * HID];
__device__ float  g_f2[NN * HID];
__device__ float  g_s [NN * HID];
__device__ float  g_Wa[HID * HID];
__device__ float  g_Wb[HID * HID];
__device__ float  g_Wc[HID * HID];
// fp16 gather tables
__device__ __half g_in16[NN * IND];
__device__ __half g_h16 [NN * HID];
__device__ __half g_f116[NN * HID];
__device__ __half g_a16 [NN * HID];

// ---------------- packed fp32x2 FMA (Blackwell FFMA2) ----------------------
__device__ __forceinline__ float2 f2fma(float2 a, float2 b, float2 c) {
    unsigned long long ua = *reinterpret_cast<unsigned long long*>(&a);
    unsigned long long ub = *reinterpret_cast<unsigned long long*>(&b);
    unsigned long long uc = *reinterpret_cast<unsigned long long*>(&c);
    unsigned long long ud;
    asm("fma.rn.f32x2 %0, %1, %2, %3;" : "=l"(ud) : "l"(ua), "l"(ub), "l"(uc));
    return *reinterpret_cast<float2*>(&ud);
}

// ---------------- graph prep ----------------
__global__ void k_zero_deg() {
    int i = blockIdx.x * blockDim.x + threadIdx.x;
    if (i < NN) { g_deg_in[i] = 0; g_deg_out[i] = 0; }
    if (i == 0) g_total = 0;
}

__global__ void k_deg(const int* __restrict__ src, const int* __restrict__ dst) {
    int e = blockIdx.x * blockDim.x + threadIdx.x;
    if (e < NE) {
        atomicAdd(&g_deg_in[dst[e]], 1);
        atomicAdd(&g_deg_out[src[e]], 1);
    }
}

__global__ void k_offsets() {
    int i = blockIdx.x * blockDim.x + threadIdx.x;
    if (i < NN) {
        int d = g_deg_in[i];
        int pos = atomicAdd(&g_total, d);
        g_row_beg[i] = pos;
        g_cursor[i]  = pos;
        g_din[i]  = rsqrtf((float)max(d, 1));
        g_dout[i] = rsqrtf((float)max(g_deg_out[i], 1));
    }
}

__global__ void k_scatter(const int* __restrict__ src, const int* __restrict__ dst) {
    int e = blockIdx.x * blockDim.x + threadIdx.x;
    if (e < NE) {
        int v = dst[e];
        int pos = atomicAdd(&g_cursor[v], 1);
        g_esrc[pos] = src[e];
    }
}

// Wa = 3*W3_0 ; Wb = -3*W3_0 + 3*W3_1 + W3_3 ; Wc = .75*W3_0 -1.5*W3_1 + .75*W3_2 + W3_4
__global__ void k_wabc(const float* __restrict__ W3) {
    int i = blockIdx.x * blockDim.x + threadIdx.x;
    if (i < HID * HID) {
        int k = i >> 6, c = i & 63;
        float w0 = W3[(k      ) * 64 + c];
        float w1 = W3[(64  + k) * 64 + c];
        float w2 = W3[(128 + k) * 64 + c];
        float w3 = W3[(192 + k) * 64 + c];
        float w4 = W3[(256 + k) * 64 + c];
        g_Wa[i] = 3.0f * w0;
        g_Wb[i] = -3.0f * w0 + 3.0f * w1 + w3;
        g_Wc[i] = 0.75f * w0 - 1.5f * w1 + 0.75f * w2 + w4;
    }
}

// ---------------- fp32 -> fp16 convert (for in_feat) -----------------------
__global__ void k_cvt(const float4* __restrict__ x, uint2* __restrict__ y, int n4) {
    int i = blockIdx.x * blockDim.x + threadIdx.x;
    if (i < n4) {
        float4 t = x[i];
        __half2 lo = __floats2half2_rn(t.x, t.y);
        __half2 hi = __floats2half2_rn(t.z, t.w);
        uint2 o;
        o.x = *reinterpret_cast<unsigned*>(&lo);
        o.y = *reinterpret_cast<unsigned*>(&hi);
        y[i] = o;
    }
}

// ---------------- spmm, fp16 gather, fp32 accumulate (warp per node) -------
__global__ void k_spmm64h(const __half2* __restrict__ x16, const float* __restrict__ gsc,
                          const float* __restrict__ base, float* __restrict__ y,
                          __half2* __restrict__ y16, int mode) {
    int w = (blockIdx.x * blockDim.x + threadIdx.x) >> 5;
    int lane = threadIdx.x & 31;
    if (w >= NN) return;
    int beg = g_row_beg[w];
    int end = beg + g_deg_in[w];
    float2 acc = make_float2(0.f, 0.f);
    #pragma unroll 4
    for (int j = beg; j < end; j++) {
        int u = g_esrc[j];
        float s = gsc[u];
        float2 t = __half22float2(x16[u * 32 + lane]);
        acc.x += t.x * s;
        acc.y += t.y * s;
    }
    float sd = g_din[w];
    float2 r;
    if (mode) {
        float2 b = *reinterpret_cast<const float2*>(base + w * 64 + lane * 2);
        r.x = b.x - acc.x * sd;
        r.y = b.y - acc.y * sd;
    } else {
        r.x = acc.x * sd;
        r.y = acc.y * sd;
    }
    *reinterpret_cast<float2*>(y + w * 64 + lane * 2) = r;
    if (y16) y16[w * 32 + lane] = __floats2half2_rn(r.x, r.y);
}

__global__ void k_spmm128h(const uint2* __restrict__ x16, const float* __restrict__ gsc,
                           float* __restrict__ y) {
    int w = (blockIdx.x * blockDim.x + threadIdx.x) >> 5;
    int lane = threadIdx.x & 31;
    if (w >= NN) return;
    int beg = g_row_beg[w];
    int end = beg + g_deg_in[w];
    float4 acc = make_float4(0.f, 0.f, 0.f, 0.f);
    #pragma unroll 4
    for (int j = beg; j < end; j++) {
        int u = g_esrc[j];
        float s = gsc[u];
        uint2 p = x16[u * 32 + lane];
        float2 lo = __half22float2(*reinterpret_cast<__half2*>(&p.x));
        float2 hi = __half22float2(*reinterpret_cast<__half2*>(&p.y));
        acc.x += lo.x * s; acc.y += lo.y * s;
        acc.z += hi.x * s; acc.w += hi.y * s;
    }
    float sd = g_din[w];
    acc.x *= sd; acc.y *= sd; acc.z *= sd; acc.w *= sd;
    *reinterpret_cast<float4*>(y + w * 128 + lane * 4) = acc;
}

// ---------------- fp32x2 tiled GEMM: C = epi(A[M,K] @ B[K,N]) --------------
#define GF_BIAS 2
#define GF_RELU 4
#define KT 32

#define GEMM_INNER(As2, Bs, acc, tx, ty)                                     \
    _Pragma("unroll")                                                        \
    for (int kk = 0; kk < KT; kk += 4) {                                     \
        float4 a4[4];                                                        \
        _Pragma("unroll")                                                    \
        for (int i = 0; i < 4; i++)                                          \
            a4[i] = *reinterpret_cast<const float4*>(&As2[ty * 4 + i][kk]);  \
        _Pragma("unroll")                                                    \
        for (int q = 0; q < 4; q++) {                                        \
            float4 bv = *reinterpret_cast<const float4*>(&Bs[kk + q][tx * 4]); \
            float2 b01 = make_float2(bv.x, bv.y);                            \
            float2 b23 = make_float2(bv.z, bv.w);                            \
            _Pragma("unroll")                                                \
            for (int i = 0; i < 4; i++) {                                    \
                float a = (q == 0) ? a4[i].x : (q == 1) ? a4[i].y             \
                        : (q == 2) ? a4[i].z : a4[i].w;                      \
                float2 aa = make_float2(a, a);                               \
                acc[i][0] = f2fma(aa, b01, acc[i][0]);                       \
                acc[i][1] = f2fma(aa, b23, acc[i][1]);                       \
            }                                                                \
        }                                                                    \
    }

__global__ void __launch_bounds__(256)
k_gemm(const float* __restrict__ A, const float* __restrict__ B,
       const float* __restrict__ bias, float* __restrict__ C,
       __half* __restrict__ Ch, int M, int K, int N, int flags) {
    __shared__ float As2[64][KT + 4];
    __shared__ float Bs[KT][68];
    int tid = threadIdx.x;
    int tx = tid & 15;
    int ty = tid >> 4;
    int rowBase = blockIdx.y * 64;
    int colBase = blockIdx.x * 64;
    float2 acc[4][2] = {};
    for (int k0 = 0; k0 < K; k0 += KT) {
        #pragma unroll 2
        for (int l = tid; l < 512; l += 256) {
            int r = l >> 3, ks = (l & 7) << 2;
            int row = rowBase + r;
            float4 v = make_float4(0.f, 0.f, 0.f, 0.f);
            if (row < M) v = *reinterpret_cast<const float4*>(A + (size_t)row * K + k0 + ks);
            *reinterpret_cast<float4*>(&As2[r][ks]) = v;
        }
        #pragma unroll 2
        for (int l = tid; l < 512; l += 256) {
            int kk = l >> 4, c = (l & 15) << 2;
            *reinterpret_cast<float4*>(&Bs[kk][c]) =
                *reinterpret_cast<const float4*>(B + (size_t)(k0 + kk) * N + colBase + c);
        }
        __syncthreads();
        GEMM_INNER(As2, Bs, acc, tx, ty)
        __syncthreads();
    }
    int col0 = colBase + tx * 4;
    float4 bb = make_float4(0.f, 0.f, 0.f, 0.f);
    if (flags & GF_BIAS) bb = *reinterpret_cast<const float4*>(bias + col0);
    #pragma unroll
    for (int i = 0; i < 4; i++) {
        int row = rowBase + ty * 4 + i;
        if (row >= M) continue;
        float4 v = make_float4(acc[i][0].x + bb.x, acc[i][0].y + bb.y,
                               acc[i][1].x + bb.z, acc[i][1].y + bb.w);
        if (flags & GF_RELU) {
            v.x = fmaxf(v.x, 0.f); v.y = fmaxf(v.y, 0.f);
            v.z = fmaxf(v.z, 0.f); v.w = fmaxf(v.w, 0.f);
        }
        *reinterpret_cast<float4*>(C + (size_t)row * N + col0) = v;
        if (Ch) {
            __half2 lo = __floats2half2_rn(v.x, v.y);
            __half2 hi = __floats2half2_rn(v.z, v.w);
            uint2 o;
            o.x = *reinterpret_cast<unsigned*>(&lo);
            o.y = *reinterpret_cast<unsigned*>(&hi);
            *reinterpret_cast<uint2*>(Ch + (size_t)row * N + col0) = o;
        }
    }
}

// ---------------- fused head: out = relu(h@Wa + f1@Wb + f2@Wc + b3) @ W4 + b4
__global__ void __launch_bounds__(256)
k_head_fused(const float* __restrict__ b3, const float* __restrict__ W4,
             const float* __restrict__ b4, float* __restrict__ out) {
    __shared__ float As2[64][KT + 4];
    __shared__ float Bs[KT][68];
    int tid = threadIdx.x;
    int tx = tid & 15;
    int ty = tid >> 4;
    int rowBase = blockIdx.x * 64;
    float2 acc[4][2] = {};
    const float* Asrc[3] = { g_h, g_f1, g_f2 };
    const float* Bsrc[3] = { g_Wa, g_Wb, g_Wc };
    for (int s3 = 0; s3 < 3; s3++) {
        const float* A = Asrc[s3];
        const float* B = Bsrc[s3];
        for (int k0 = 0; k0 < 64; k0 += KT) {
            #pragma unroll 2
            for (int l = tid; l < 512; l += 256) {
                int r = l >> 3, ks = (l & 7) << 2;
                int row = rowBase + r;
                float4 v = make_float4(0.f, 0.f, 0.f, 0.f);
                if (row < NN) v = *reinterpret_cast<const float4*>(A + (size_t)row * 64 + k0 + ks);
                *reinterpret_cast<float4*>(&As2[r][ks]) = v;
            }
            #pragma unroll 2
            for (int l = tid; l < 512; l += 256) {
                int kk = l >> 4, c = (l & 15) << 2;
                *reinterpret_cast<float4*>(&Bs[kk][c]) =
                    *reinterpret_cast<const float4*>(B + (size_t)(k0 + kk) * 64 + c);
            }
            __syncthreads();
            GEMM_INNER(As2, Bs, acc, tx, ty)
            __syncthreads();
        }
    }
    int col0 = tx * 4;
    float4 bb = *reinterpret_cast<const float4*>(b3 + col0);
    float w40[4], w41[4];
    #pragma unroll
    for (int jj = 0; jj < 4; jj++) {
        w40[jj] = W4[(col0 + jj) * 2];
        w41[jj] = W4[(col0 + jj) * 2 + 1];
    }
    float o0 = b4[0], o1 = b4[1];
    #pragma unroll
    for (int i = 0; i < 4; i++) {
        float z0 = fmaxf(acc[i][0].x + bb.x, 0.f);
        float z1 = fmaxf(acc[i][0].y + bb.y, 0.f);
        float z2 = fmaxf(acc[i][1].x + bb.z, 0.f);
        float z3 = fmaxf(acc[i][1].y + bb.w, 0.f);
        float p0 = z0 * w40[0] + z1 * w40[1] + z2 * w40[2] + z3 * w40[3];
        float p1 = z0 * w41[0] + z1 * w41[1] + z2 * w41[2] + z3 * w41[3];
        #pragma unroll
        for (int off = 8; off >= 1; off >>= 1) {
            p0 += __shfl_down_sync(0xffffffffu, p0, off, 16);
            p1 += __shfl_down_sync(0xffffffffu, p1, off, 16);
        }
        int row = rowBase + ty * 4 + i;
        if (tx == 0 && row < NN) {
            out[row * 2]     = p0 + o0;
            out[row * 2 + 1] = p1 + o1;
        }
    }
}

// ---------------- launch (two forked streams inside capture) ---------------
extern "C" void kernel_launch(void* const* d_in, const int* in_sizes, int n_in,
                              void* d_out, int out_size) {
    const float* in_feat = (const float*)d_in[0];
    const int*   src     = (const int*)d_in[1];
    const int*   dst     = (const int*)d_in[2];
    const float* W1 = (const float*)d_in[3];
    const float* b1 = (const float*)d_in[4];
    const float* W2 = (const float*)d_in[5];
    const float* b2 = (const float*)d_in[6];
    const float* W3 = (const float*)d_in[7];
    const float* b3 = (const float*)d_in[8];
    const float* W4 = (const float*)d_in[9];
    const float* b4 = (const float*)d_in[10];
    const float* Wg1 = (const float*)d_in[11];
    const float* bg1 = (const float*)d_in[12];
    const float* Wg2 = (const float*)d_in[13];
    const float* bg2 = (const float*)d_in[14];

    float* out = (float*)d_out;          // [NN,2]
    float* emb = out + NN * 2;           // [NN,128]

    float  *p_h, *p_f1, *p_f2, *p_s, *p_bufA, *p_bufB, *p_bufC, *p_din, *p_dout;
    __half *p_in16, *p_h16, *p_f116, *p_a16;
    cudaGetSymbolAddress((void**)&p_h,    g_h);
    cudaGetSymbolAddress((void**)&p_f1,   g_f1);
    cudaGetSymbolAddress((void**)&p_f2,   g_f2);
    cudaGetSymbolAddress((void**)&p_s,    g_s);
    cudaGetSymbolAddress((void**)&p_bufA, g_bufA);
    cudaGetSymbolAddress((void**)&p_bufB, g_bufB);
    cudaGetSymbolAddress((void**)&p_bufC, g_bufC);
    cudaGetSymbolAddress((void**)&p_din,  g_din);
    cudaGetSymbolAddress((void**)&p_dout, g_dout);
    cudaGetSymbolAddress((void**)&p_in16, g_in16);
    cudaGetSymbolAddress((void**)&p_h16,  g_h16);
    cudaGetSymbolAddress((void**)&p_f116, g_f116);
    cudaGetSymbolAddress((void**)&p_a16,  g_a16);

    // streams/events created once on the uncaptured correctness call; reused
    // for the capture call (creation during capture is illegal). Work per call
    // is identical every call.
    static cudaStream_t s1 = nullptr, s2 = nullptr;
    static cudaEvent_t evRoot, evGraph, evCvt, evS1, evS2;
    if (!s1) {
        cudaStreamCreateWithFlags(&s1, cudaStreamNonBlocking);
        cudaStreamCreateWithFlags(&s2, cudaStreamNonBlocking);
        cudaEventCreateWithFlags(&evRoot,  cudaEventDisableTiming);
        cudaEventCreateWithFlags(&evGraph, cudaEventDisableTiming);
        cudaEventCreateWithFlags(&evCvt,   cudaEventDisableTiming);
        cudaEventCreateWithFlags(&evS1,    cudaEventDisableTiming);
        cudaEventCreateWithFlags(&evS2,    cudaEventDisableTiming);
    }

    const int TB = 256;
    int nBlkN = (NN + TB - 1) / TB;
    int nBlkE = (NE + TB - 1) / TB;
    int spmmBlocks = (NN * 32 + TB - 1) / TB;
    dim3 g64(1, (NN + 63) / 64);
    dim3 g128(2, (NN + 63) / 64);
    int hBlocks = (NN + 63) / 64;

    // ---- fork ----
    cudaEventRecord(evRoot, 0);
    cudaStreamWaitEvent(s1, evRoot, 0);
    cudaStreamWaitEvent(s2, evRoot, 0);

    // ---- stream0: graph prep (atomic/LSU bound) ----
    k_zero_deg<<<nBlkN, TB>>>();
    k_deg<<<nBlkE, TB>>>(src, dst);
    k_offsets<<<nBlkN, TB>>>();
    k_scatter<<<nBlkE, TB>>>(src, dst);
    cudaEventRecord(evGraph, 0);

    // ---- s1: weight prep + MLP front end (FMA bound; overlaps prep) ----
    k_wabc<<<16, TB, 0, s1>>>(W3);
    k_cvt<<<(NN * 32 + TB - 1) / TB, TB, 0, s1>>>((const float4*)in_feat, (uint2*)p_in16, NN * 32);
    cudaEventRecord(evCvt, s1);
    k_gemm<<<g64, 256, 0, s1>>>(in_feat, W1, b1, p_s, nullptr, NN, 128, 64, GF_BIAS | GF_RELU);
    k_gemm<<<g64, 256, 0, s1>>>(p_s, W2, b2, p_h, p_h16, NN, 64, 64, GF_BIAS | GF_RELU);

    // ---- s1: band branch (needs graph) ----
    cudaStreamWaitEvent(s1, evGraph, 0);
    k_spmm64h<<<spmmBlocks, TB, 0, s1>>>((const __half2*)p_h16,  p_din, p_h,  p_f1, (__half2*)p_f116, 1);
    k_spmm64h<<<spmmBlocks, TB, 0, s1>>>((const __half2*)p_f116, p_din, p_f1, p_f2, nullptr, 1);
    k_head_fused<<<hBlocks, 256, 0, s1>>>(b3, W4, b4, out);
    cudaEventRecord(evS1, s1);

    // ---- s2: GCN branch (needs graph + in16) ----
    cudaStreamWaitEvent(s2, evGraph, 0);
    cudaStreamWaitEvent(s2, evCvt, 0);
    k_spmm128h<<<spmmBlocks, TB, 0, s2>>>((const uint2*)p_in16, p_dout, p_bufB);
    k_gemm<<<g64, 256, 0, s2>>>(p_bufB, Wg1, bg1, p_bufA, p_a16, NN, 128, 64, GF_BIAS | GF_RELU);
    k_spmm64h<<<spmmBlocks, TB, 0, s2>>>((const __half2*)p_a16, p_dout, nullptr, p_bufC, nullptr, 0);
    k_gemm<<<g128, 256, 0, s2>>>(p_bufC, Wg2, bg2, emb, nullptr, NN, 64, 128, GF_BIAS);
    cudaEventRecord(evS2, s2);

    // ---- join ----
    cudaStreamWaitEvent(0, evS1, 0);
    cudaStreamWaitEvent(0, evS2, 0);
}